// round 4
// baseline (speedup 1.0000x reference)
#include <cuda_runtime.h>
#include <stdint.h>

#define F_IN 128
#define D1   64
#define H1   8
#define C2   40
#define NMAX 100352
#define MMAX 1703936   // E + N upper bound
#define LOG2E 1.44269504088896f

typedef unsigned long long u64;

// ---------------- scratch (static device allocations) ----------------
__device__ __align__(16) float g_h1 [NMAX * D1];
__device__ __align__(16) float g_hm [NMAX * D1];
__device__ __align__(16) float g_a1s[NMAX * H1];
__device__ __align__(16) float g_a1d[NMAX * H1];
__device__ __align__(16) float g_h2 [NMAX * C2];
__device__ __align__(16) float g_a2s[NMAX];
__device__ __align__(16) float g_a2d[NMAX];
__device__ __align__(16) int   g_deg[NMAX];
__device__ __align__(16) int   g_cur[NMAX];
__device__ __align__(16) int   g_row[NMAX + 1];
__device__ __align__(16) int   g_bsum[256];
__device__ __align__(16) int   g_csr[MMAX];
__device__ int g_is32;

// ---------------- helpers ----------------
__device__ __forceinline__ float elu1(float v)  { return v > 0.f ? v : (__expf(v) - 1.f); }
__device__ __forceinline__ float ex2a(float x)  { float r; asm("ex2.approx.ftz.f32 %0,%1;" : "=f"(r) : "f"(x)); return r; }
__device__ __forceinline__ u64  dup2(float x)   { u64 r; asm("mov.b64 %0,{%1,%1};" : "=l"(r) : "f"(x)); return r; }
__device__ __forceinline__ void fma2(u64& d, u64 a, u64 b) { asm("fma.rn.f32x2 %0,%1,%2,%0;" : "+l"(d) : "l"(a), "l"(b)); }
__device__ __forceinline__ float2 un2(u64 v)    { float2 f; asm("mov.b64 {%0,%1},%2;" : "=f"(f.x), "=f"(f.y) : "l"(v)); return f; }

__device__ __forceinline__ int edge_at(const void* ei, int idx, int is32)
{
    return is32 ? ((const int*)ei)[idx] : (int)((const long long*)ei)[idx];
}

// ---------------- init: deg=1 (self-loop precounted) + dtype detect --------
__global__ void k_init(const void* ei, int N)
{
    int i = blockIdx.x * blockDim.x + threadIdx.x;
    if (i < N) g_deg[i] = 1;
    if (i == 0) {
        const long long* p = (const long long*)ei;
        int bad = 0;
#pragma unroll 8
        for (int k = 0; k < 64; k++) {
            long long v = p[k];
            if (v < 0 || v >= (long long)N) bad = 1;
        }
        g_is32 = bad;
    }
}

// ---------------- GEMM1: h1 = x @ W1  (+ scaled att-dot epilogue) ----------
__global__ __launch_bounds__(256) void k_gemm1(
    const float* __restrict__ x, const float* __restrict__ W,
    const float* __restrict__ atts, const float* __restrict__ attd, int N)
{
    __shared__ __align__(16) float Ws[32][64];
    __shared__ __align__(16) float xsT[32][132];
    __shared__ float sAs[64], sAd[64];

    int tid = threadIdx.x;
    if (tid < 64) { sAs[tid] = atts[tid] * LOG2E; sAd[tid] = attd[tid] * LOG2E; }

    int rg = tid >> 3;        // 0..31
    int cg = tid & 7;         // 0..7
    int rowBase = blockIdx.x * 128;

    u64 acc[4][4];
#pragma unroll
    for (int i = 0; i < 4; i++)
#pragma unroll
        for (int c = 0; c < 4; c++) acc[i][c] = 0ull;

    const float4* x4 = (const float4*)x;
    const float4* W4 = (const float4*)W;

    for (int kc = 0; kc < 4; kc++) {
        __syncthreads();
#pragma unroll
        for (int i = 0; i < 2; i++) {
            int f = tid + i * 256;
            int kk = f >> 4, qj = f & 15;
            ((float4*)&Ws[kk][0])[qj] = W4[(kc * 32 + kk) * 16 + qj];
        }
#pragma unroll
        for (int i = 0; i < 4; i++) {
            int f = tid + i * 256;
            int r = f >> 3, q = f & 7;
            int gr = rowBase + r;
            float4 xv = make_float4(0.f, 0.f, 0.f, 0.f);
            if (gr < N) xv = x4[(size_t)gr * 32 + kc * 8 + q];
            xsT[q * 4 + 0][r] = xv.x;
            xsT[q * 4 + 1][r] = xv.y;
            xsT[q * 4 + 2][r] = xv.z;
            xsT[q * 4 + 3][r] = xv.w;
        }
        __syncthreads();
#pragma unroll
        for (int kk = 0; kk < 32; kk++) {
            float4 xv = *(const float4*)&xsT[kk][rg * 4];
            ulonglong2 wA = *(const ulonglong2*)&Ws[kk][cg * 8];
            ulonglong2 wB = *(const ulonglong2*)&Ws[kk][cg * 8 + 4];
            u64 xd[4] = {dup2(xv.x), dup2(xv.y), dup2(xv.z), dup2(xv.w)};
#pragma unroll
            for (int i = 0; i < 4; i++) {
                fma2(acc[i][0], xd[i], wA.x);
                fma2(acc[i][1], xd[i], wA.y);
                fma2(acc[i][2], xd[i], wB.x);
                fma2(acc[i][3], xd[i], wB.y);
            }
        }
    }

#pragma unroll
    for (int i = 0; i < 4; i++) {
        int row = rowBase + rg * 4 + i;
        if (row >= N) continue;
        float o[8];
#pragma unroll
        for (int c = 0; c < 4; c++) {
            float2 v = un2(acc[i][c]);
            o[2 * c] = v.x; o[2 * c + 1] = v.y;
        }
        float* hp = g_h1 + (size_t)row * 64 + cg * 8;
        ((float4*)hp)[0] = make_float4(o[0], o[1], o[2], o[3]);
        ((float4*)hp)[1] = make_float4(o[4], o[5], o[6], o[7]);
        float s = 0.f, d = 0.f;
#pragma unroll
        for (int c = 0; c < 8; c++) {
            s += o[c] * sAs[cg * 8 + c];
            d += o[c] * sAd[cg * 8 + c];
        }
        g_a1s[row * 8 + cg] = s;
        g_a1d[row * 8 + cg] = d;
    }
}

// ---------------- CSR build ----------------
__global__ void k_deg(const void* __restrict__ ei, int E)
{
    int base = (blockIdx.x * blockDim.x + threadIdx.x) * 4;
    if (base >= E) return;
    int is32 = g_is32;
    if (base + 4 <= E) {
        if (is32) {
            if ((E & 3) == 0) {
                int4 v = *(const int4*)((const int*)ei + E + base);
                atomicAdd(&g_deg[v.x], 1); atomicAdd(&g_deg[v.y], 1);
                atomicAdd(&g_deg[v.z], 1); atomicAdd(&g_deg[v.w], 1);
            } else {
                const int* p = (const int*)ei + E + base;
#pragma unroll
                for (int k = 0; k < 4; k++) atomicAdd(&g_deg[p[k]], 1);
            }
        } else {
            if ((E & 1) == 0) {
                const ulonglong2* p = (const ulonglong2*)((const long long*)ei + E + base);
                ulonglong2 a = p[0], b = p[1];
                atomicAdd(&g_deg[(int)a.x], 1); atomicAdd(&g_deg[(int)a.y], 1);
                atomicAdd(&g_deg[(int)b.x], 1); atomicAdd(&g_deg[(int)b.y], 1);
            } else {
                const long long* p = (const long long*)ei + E + base;
#pragma unroll
                for (int k = 0; k < 4; k++) atomicAdd(&g_deg[(int)p[k]], 1);
            }
        }
    } else {
        for (int k = 0; k < E - base; k++)
            atomicAdd(&g_deg[edge_at(ei, E + base + k, is32)], 1);
    }
}

__global__ __launch_bounds__(1024) void k_bsum(int N)
{
    __shared__ int sm[1024];
    int i = blockIdx.x * 1024 + threadIdx.x;
    sm[threadIdx.x] = (i < N) ? g_deg[i] : 0;
    __syncthreads();
    for (int s = 512; s > 0; s >>= 1) {
        if (threadIdx.x < s) sm[threadIdx.x] += sm[threadIdx.x + s];
        __syncthreads();
    }
    if (threadIdx.x == 0) g_bsum[blockIdx.x] = sm[0];
}

__global__ __launch_bounds__(1024) void k_scan3(int N, int M)
{
    __shared__ int sm[1024];
    __shared__ int ws[4];
    __shared__ int s_off;
    int tid = threadIdx.x;
    int bid = blockIdx.x;

    if (tid < 128) {
        int v2 = (tid < bid) ? g_bsum[tid] : 0;
#pragma unroll
        for (int m = 16; m > 0; m >>= 1)
            v2 += __shfl_xor_sync(0xffffffffu, v2, m);
        if ((tid & 31) == 0) ws[tid >> 5] = v2;
    }
    __syncthreads();
    if (tid == 0) s_off = ws[0] + ws[1] + ws[2] + ws[3];

    int i = bid * 1024 + tid;
    int v = (i < N) ? g_deg[i] : 0;
    sm[tid] = v;
    __syncthreads();
    for (int off = 1; off < 1024; off <<= 1) {
        int t = (tid >= off) ? sm[tid - off] : 0;
        __syncthreads();
        sm[tid] += t;
        __syncthreads();
    }
    if (i < N) {
        int excl = s_off + sm[tid] - v;
        g_row[i] = excl;
        g_cur[i] = excl;
    }
    if (bid == gridDim.x - 1 && tid == 0) g_row[N] = M;
}

__global__ void k_scatter(const void* __restrict__ ei, int E, int M)
{
    int base = (blockIdx.x * blockDim.x + threadIdx.x) * 4;
    if (base >= M) return;
    int is32 = g_is32;
    if (base + 4 <= E && is32 && (E & 3) == 0) {
        int4 sv = *(const int4*)((const int*)ei + base);
        int4 dv = *(const int4*)((const int*)ei + E + base);
        g_csr[atomicAdd(&g_cur[dv.x], 1)] = sv.x;
        g_csr[atomicAdd(&g_cur[dv.y], 1)] = sv.y;
        g_csr[atomicAdd(&g_cur[dv.z], 1)] = sv.z;
        g_csr[atomicAdd(&g_cur[dv.w], 1)] = sv.w;
    } else if (base + 4 <= E && !is32 && (E & 1) == 0) {
        const ulonglong2* sp = (const ulonglong2*)((const long long*)ei + base);
        const ulonglong2* dp = (const ulonglong2*)((const long long*)ei + E + base);
        ulonglong2 s0 = sp[0], s1 = sp[1], d0 = dp[0], d1 = dp[1];
        g_csr[atomicAdd(&g_cur[(int)d0.x], 1)] = (int)s0.x;
        g_csr[atomicAdd(&g_cur[(int)d0.y], 1)] = (int)s0.y;
        g_csr[atomicAdd(&g_cur[(int)d1.x], 1)] = (int)s1.x;
        g_csr[atomicAdd(&g_cur[(int)d1.y], 1)] = (int)s1.y;
    } else {
        int cnt = min(4, M - base);
        for (int k = 0; k < cnt; k++) {
            int idx = base + k;
            int s, d;
            if (idx < E) { s = edge_at(ei, idx, is32); d = edge_at(ei, E + idx, is32); }
            else         { s = d = idx - E; }
            g_csr[atomicAdd(&g_cur[d], 1)] = s;
        }
    }
}

// ---- layer-1 gather: 4 lanes/node, 2 heads/lane, single pass, f32x2 ------
__global__ __launch_bounds__(256) void k_gather1(const float* __restrict__ b1, int N)
{
    int t = blockIdx.x * 256 + threadIdx.x;
    int n = t >> 2, p = t & 3;
    if (n >= N) return;
    int beg = g_row[n], end = g_row[n + 1];
    float2 ad = *(const float2*)(g_a1d + n * 8 + p * 2);

    u64 A[8];
#pragma unroll
    for (int k = 0; k < 8; k++) A[k] = 0ull;
    float s0 = 0.f, s1 = 0.f;

    for (int e = beg; e < end; e++) {
        int s = g_csr[e];
        float2 as = *(const float2*)(g_a1s + s * 8 + p * 2);
        float v0 = as.x + ad.x, v1 = as.y + ad.y;
        float w0 = ex2a(fmaxf(v0, 0.2f * v0));
        float w1 = ex2a(fmaxf(v1, 0.2f * v1));
        s0 += w0; s1 += w1;
        u64 W0 = dup2(w0), W1 = dup2(w1);
        const ulonglong2* hp = (const ulonglong2*)(g_h1 + (size_t)s * 64 + p * 16);
        ulonglong2 q0 = hp[0], q1 = hp[1], q2 = hp[2], q3 = hp[3];
        fma2(A[0], q0.x, W0); fma2(A[1], q0.y, W0);
        fma2(A[2], q1.x, W0); fma2(A[3], q1.y, W0);
        fma2(A[4], q2.x, W1); fma2(A[5], q2.y, W1);
        fma2(A[6], q3.x, W1); fma2(A[7], q3.y, W1);
    }
    float i0 = 1.f / (s0 + 1e-16f), i1 = 1.f / (s1 + 1e-16f);

    const float2* bp = (const float2*)(b1 + p * 16);
    float* op = g_hm + (size_t)n * 64 + p * 16;
#pragma unroll
    for (int k = 0; k < 8; k++) {
        float inv = (k < 4) ? i0 : i1;
        float2 a = un2(A[k]);
        float2 bb = bp[k];
        float2 r;
        r.x = elu1(a.x * inv + bb.x);
        r.y = elu1(a.y * inv + bb.y);
        ((float2*)op)[k] = r;
    }
}

// ---------------- GEMM2: h2 = hm @ W2 (+ scaled att-dot epilogue) ----------
__global__ __launch_bounds__(256) void k_gemm2(
    const float* __restrict__ W2, const float* __restrict__ as2,
    const float* __restrict__ ad2, int N)
{
    __shared__ __align__(16) float Ws[64][40];
    __shared__ __align__(16) float xsT[16][260];
    __shared__ float sA[40], sD[40];

    int tid = threadIdx.x;
    if (tid < 40) { sA[tid] = as2[tid] * LOG2E; sD[tid] = ad2[tid] * LOG2E; }
    for (int f = tid; f < 640; f += 256)
        ((float4*)&Ws[0][0])[f] = ((const float4*)W2)[f];

    int rg = tid >> 2;   // 0..63
    int cg = tid & 3;    // 0..3
    int rowBase = blockIdx.x * 256;

    u64 acc[4][5];
#pragma unroll
    for (int i = 0; i < 4; i++)
#pragma unroll
        for (int c = 0; c < 5; c++) acc[i][c] = 0ull;

    const float4* hm4 = (const float4*)g_hm;

    for (int kc = 0; kc < 4; kc++) {
        __syncthreads();
#pragma unroll
        for (int i = 0; i < 4; i++) {
            int f = tid + i * 256;
            int r = f >> 2, q = f & 3;
            int gr = rowBase + r;
            float4 xv = make_float4(0.f, 0.f, 0.f, 0.f);
            if (gr < N) xv = hm4[(size_t)gr * 16 + kc * 4 + q];
            xsT[q * 4 + 0][r] = xv.x;
            xsT[q * 4 + 1][r] = xv.y;
            xsT[q * 4 + 2][r] = xv.z;
            xsT[q * 4 + 3][r] = xv.w;
        }
        __syncthreads();
#pragma unroll
        for (int kk = 0; kk < 16; kk++) {
            float4 xv = *(const float4*)&xsT[kk][rg * 4];
            const u64* wp = (const u64*)&Ws[kc * 16 + kk][cg * 10];
            u64 w0 = wp[0], w1 = wp[1], w2 = wp[2], w3 = wp[3], w4 = wp[4];
            u64 xd[4] = {dup2(xv.x), dup2(xv.y), dup2(xv.z), dup2(xv.w)};
#pragma unroll
            for (int i = 0; i < 4; i++) {
                fma2(acc[i][0], xd[i], w0);
                fma2(acc[i][1], xd[i], w1);
                fma2(acc[i][2], xd[i], w2);
                fma2(acc[i][3], xd[i], w3);
                fma2(acc[i][4], xd[i], w4);
            }
        }
    }

#pragma unroll
    for (int i = 0; i < 4; i++) {
        int row = rowBase + rg * 4 + i;
        float o[10];
#pragma unroll
        for (int c = 0; c < 5; c++) {
            float2 v = un2(acc[i][c]);
            o[2 * c] = v.x; o[2 * c + 1] = v.y;
        }
        float ps = 0.f, pd = 0.f;
#pragma unroll
        for (int c = 0; c < 10; c++) {
            ps += o[c] * sA[cg * 10 + c];
            pd += o[c] * sD[cg * 10 + c];
        }
        ps += __shfl_xor_sync(0xffffffffu, ps, 1);
        ps += __shfl_xor_sync(0xffffffffu, ps, 2);
        pd += __shfl_xor_sync(0xffffffffu, pd, 1);
        pd += __shfl_xor_sync(0xffffffffu, pd, 2);
        if (row < N) {
            u64* hp = (u64*)(g_h2 + (size_t)row * 40 + cg * 10);
#pragma unroll
            for (int c = 0; c < 5; c++) hp[c] = acc[i][c];
            if (cg == 0) { g_a2s[row] = ps; g_a2d[row] = pd; }
        }
    }
}

// ---- layer-2 gather: 4 lanes/node, 10 classes/lane, f32x2 + log_softmax ---
__global__ __launch_bounds__(256) void k_gather2(
    const float* __restrict__ b2, float* __restrict__ out, int N)
{
    int t = blockIdx.x * 256 + threadIdx.x;
    int n = t >> 2, p = t & 3;
    bool valid = (n < N);
    if (!valid) n = N - 1;
    int beg = g_row[n], end = g_row[n + 1];
    float ad = g_a2d[n];

    u64 A[5] = {0ull, 0ull, 0ull, 0ull, 0ull};
    float ssum = 0.f;
    for (int e = beg; e < end; e++) {
        int s = g_csr[e];
        float v = g_a2s[s] + ad;
        float w = ex2a(fmaxf(v, 0.2f * v));
        ssum += w;
        u64 W = dup2(w);
        const u64* hp = (const u64*)(g_h2 + (size_t)s * 40 + p * 10);
        fma2(A[0], hp[0], W);
        fma2(A[1], hp[1], W);
        fma2(A[2], hp[2], W);
        fma2(A[3], hp[3], W);
        fma2(A[4], hp[4], W);
    }
    float inv = 1.f / (ssum + 1e-16f);

    const float2* bp = (const float2*)(b2 + p * 10);
    float o[10];
    float mx = -1e30f;
#pragma unroll
    for (int c = 0; c < 5; c++) {
        float2 a = un2(A[c]);
        float2 bb = bp[c];
        o[2 * c]     = a.x * inv + bb.x;
        o[2 * c + 1] = a.y * inv + bb.y;
        mx = fmaxf(mx, fmaxf(o[2 * c], o[2 * c + 1]));
    }
    mx = fmaxf(mx, __shfl_xor_sync(0xffffffffu, mx, 1));
    mx = fmaxf(mx, __shfl_xor_sync(0xffffffffu, mx, 2));
    float se = 0.f;
#pragma unroll
    for (int j = 0; j < 10; j++) se += __expf(o[j] - mx);
    se += __shfl_xor_sync(0xffffffffu, se, 1);
    se += __shfl_xor_sync(0xffffffffu, se, 2);
    float lse = mx + logf(se);

    if (valid) {
        float2* op = (float2*)(out + (size_t)n * 40 + p * 10);
#pragma unroll
        for (int c = 0; c < 5; c++) {
            float2 r;
            r.x = o[2 * c] - lse;
            r.y = o[2 * c + 1] - lse;
            op[c] = r;
        }
    }
}

// ---------------- launch ----------------
extern "C" void kernel_launch(void* const* d_in, const int* in_sizes, int n_in,
                              void* d_out, int out_size)
{
    const float* x    = (const float*)d_in[0];
    const void*  ei   = d_in[1];
    const float* W1   = (const float*)d_in[2];
    const float* as1  = (const float*)d_in[3];
    const float* ad1  = (const float*)d_in[4];
    const float* b1   = (const float*)d_in[5];
    const float* W2   = (const float*)d_in[6];
    const float* as2  = (const float*)d_in[7];
    const float* ad2  = (const float*)d_in[8];
    const float* b2   = (const float*)d_in[9];
    float*       out  = (float*)d_out;

    int N = in_sizes[0] / F_IN;
    int E = in_sizes[1] / 2;
    int M = E + N;
    int NB = (N + 1023) / 1024;

    static cudaStream_t s_side = nullptr;
    static cudaEvent_t  ev_fork = nullptr, ev_join = nullptr;
    if (!s_side) {
        cudaStreamCreateWithFlags(&s_side, cudaStreamNonBlocking);
        cudaEventCreateWithFlags(&ev_fork, cudaEventDisableTiming);
        cudaEventCreateWithFlags(&ev_join, cudaEventDisableTiming);
    }

    // fork: gemm1 on side stream, concurrent with CSR build
    cudaEventRecord(ev_fork, 0);
    cudaStreamWaitEvent(s_side, ev_fork, 0);
    k_gemm1<<<(N + 127) / 128, 256, 0, s_side>>>(x, W1, as1, ad1, N);
    cudaEventRecord(ev_join, s_side);

    // main chain: CSR build
    k_init<<<(N + 255) / 256, 256>>>(ei, N);
    k_deg<<<(E / 4 + 256) / 256, 256>>>(ei, E);
    k_bsum<<<NB, 1024>>>(N);
    k_scan3<<<NB, 1024>>>(N, M);
    k_scatter<<<(M / 4 + 256) / 256, 256>>>(ei, E, M);

    // join, then attention layers
    cudaStreamWaitEvent(0, ev_join, 0);
    k_gather1<<<(N * 4 + 255) / 256, 256>>>(b1, N);
    k_gemm2<<<(N + 255) / 256, 256>>>(W2, as2, ad2, N);
    k_gather2<<<(N * 4 + 255) / 256, 256>>>(b2, out, N);
}

// round 5
// speedup vs baseline: 1.1100x; 1.1100x over previous
#include <cuda_runtime.h>
#include <stdint.h>

#define F_IN 128
#define D1   64
#define H1   8
#define C2   40
#define NMAX 100352
#define MMAX 1703936   // E + N upper bound
#define LOG2E 1.44269504088896f

typedef unsigned long long u64;

// ---------------- scratch (static device allocations) ----------------
__device__ __align__(16) float g_h1 [NMAX * D1];
__device__ __align__(16) float g_hm [NMAX * D1];
__device__ __align__(16) float g_a1s[NMAX * H1];
__device__ __align__(16) float g_a1d[NMAX * H1];
__device__ __align__(16) float g_h2 [NMAX * C2];
__device__ __align__(16) float g_a2s[NMAX];
__device__ __align__(16) float g_a2d[NMAX];
__device__ __align__(16) int   g_deg[NMAX];
__device__ __align__(16) int   g_cur[NMAX];
__device__ __align__(16) int   g_row[NMAX + 1];
__device__ __align__(16) int   g_bsum[256];
__device__ __align__(16) int   g_csr[MMAX];
__device__ int g_is32;

// ---------------- helpers ----------------
__device__ __forceinline__ float elu1(float v)  { return v > 0.f ? v : (__expf(v) - 1.f); }
__device__ __forceinline__ float ex2a(float x)  { float r; asm("ex2.approx.ftz.f32 %0,%1;" : "=f"(r) : "f"(x)); return r; }
__device__ __forceinline__ u64  dup2(float x)   { u64 r; asm("mov.b64 %0,{%1,%1};" : "=l"(r) : "f"(x)); return r; }
__device__ __forceinline__ void fma2(u64& d, u64 a, u64 b) { asm("fma.rn.f32x2 %0,%1,%2,%0;" : "+l"(d) : "l"(a), "l"(b)); }
__device__ __forceinline__ float2 un2(u64 v)    { float2 f; asm("mov.b64 {%0,%1},%2;" : "=f"(f.x), "=f"(f.y) : "l"(v)); return f; }

__device__ __forceinline__ int edge_at(const void* ei, int idx, int is32)
{
    return is32 ? ((const int*)ei)[idx] : (int)((const long long*)ei)[idx];
}

// ---------------- init: zero deg + dtype detect ----------------
__global__ void k_init(const void* ei, int N)
{
    int i = blockIdx.x * blockDim.x + threadIdx.x;
    if (i < N) g_deg[i] = 0;
    if (i == 0) {
        const long long* p = (const long long*)ei;
        int bad = 0;
#pragma unroll 8
        for (int k = 0; k < 64; k++) {
            long long v = p[k];
            if (v < 0 || v >= (long long)N) bad = 1;
        }
        g_is32 = bad;
    }
}

// ---------------- GEMM1: h1 = x @ W1  (+ scaled att-dot epilogue) ----------
__global__ __launch_bounds__(256) void k_gemm1(
    const float* __restrict__ x, const float* __restrict__ W,
    const float* __restrict__ atts, const float* __restrict__ attd, int N)
{
    __shared__ __align__(16) float Ws[32][64];
    __shared__ __align__(16) float xsT[32][132];
    __shared__ float sAs[64], sAd[64];

    int tid = threadIdx.x;
    if (tid < 64) { sAs[tid] = atts[tid] * LOG2E; sAd[tid] = attd[tid] * LOG2E; }

    int rg = tid >> 3;        // 0..31
    int cg = tid & 7;         // 0..7
    int rowBase = blockIdx.x * 128;

    u64 acc[4][4];
#pragma unroll
    for (int i = 0; i < 4; i++)
#pragma unroll
        for (int c = 0; c < 4; c++) acc[i][c] = 0ull;

    const float4* x4 = (const float4*)x;
    const float4* W4 = (const float4*)W;

    for (int kc = 0; kc < 4; kc++) {
        __syncthreads();
#pragma unroll
        for (int i = 0; i < 2; i++) {
            int f = tid + i * 256;
            int kk = f >> 4, qj = f & 15;
            ((float4*)&Ws[kk][0])[qj] = W4[(kc * 32 + kk) * 16 + qj];
        }
#pragma unroll
        for (int i = 0; i < 4; i++) {
            int f = tid + i * 256;
            int r = f >> 3, q = f & 7;
            int gr = rowBase + r;
            float4 xv = make_float4(0.f, 0.f, 0.f, 0.f);
            if (gr < N) xv = x4[(size_t)gr * 32 + kc * 8 + q];
            xsT[q * 4 + 0][r] = xv.x;
            xsT[q * 4 + 1][r] = xv.y;
            xsT[q * 4 + 2][r] = xv.z;
            xsT[q * 4 + 3][r] = xv.w;
        }
        __syncthreads();
#pragma unroll
        for (int kk = 0; kk < 32; kk++) {
            float4 xv = *(const float4*)&xsT[kk][rg * 4];
            ulonglong2 wA = *(const ulonglong2*)&Ws[kk][cg * 8];
            ulonglong2 wB = *(const ulonglong2*)&Ws[kk][cg * 8 + 4];
            u64 xd[4] = {dup2(xv.x), dup2(xv.y), dup2(xv.z), dup2(xv.w)};
#pragma unroll
            for (int i = 0; i < 4; i++) {
                fma2(acc[i][0], xd[i], wA.x);
                fma2(acc[i][1], xd[i], wA.y);
                fma2(acc[i][2], xd[i], wB.x);
                fma2(acc[i][3], xd[i], wB.y);
            }
        }
    }

#pragma unroll
    for (int i = 0; i < 4; i++) {
        int row = rowBase + rg * 4 + i;
        if (row >= N) continue;
        float o[8];
#pragma unroll
        for (int c = 0; c < 4; c++) {
            float2 v = un2(acc[i][c]);
            o[2 * c] = v.x; o[2 * c + 1] = v.y;
        }
        float* hp = g_h1 + (size_t)row * 64 + cg * 8;
        ((float4*)hp)[0] = make_float4(o[0], o[1], o[2], o[3]);
        ((float4*)hp)[1] = make_float4(o[4], o[5], o[6], o[7]);
        float s = 0.f, d = 0.f;
#pragma unroll
        for (int c = 0; c < 8; c++) {
            s += o[c] * sAs[cg * 8 + c];
            d += o[c] * sAd[cg * 8 + c];
        }
        g_a1s[row * 8 + cg] = s;
        g_a1d[row * 8 + cg] = d;
    }
}

// ---------------- CSR build (scalar, 1 edge/thread) ----------------
__global__ void k_deg(const void* __restrict__ ei, int E, int M)
{
    int i = blockIdx.x * blockDim.x + threadIdx.x;
    if (i >= M) return;
    int is32 = g_is32;
    int d = (i < E) ? edge_at(ei, E + i, is32) : (i - E);
    atomicAdd(&g_deg[d], 1);
}

__global__ __launch_bounds__(1024) void k_bsum(int N)
{
    __shared__ int sm[1024];
    int i = blockIdx.x * 1024 + threadIdx.x;
    sm[threadIdx.x] = (i < N) ? g_deg[i] : 0;
    __syncthreads();
    for (int s = 512; s > 0; s >>= 1) {
        if (threadIdx.x < s) sm[threadIdx.x] += sm[threadIdx.x + s];
        __syncthreads();
    }
    if (threadIdx.x == 0) g_bsum[blockIdx.x] = sm[0];
}

__global__ __launch_bounds__(1024) void k_scan3(int N, int M)
{
    __shared__ int sm[1024];
    __shared__ int ws[4];
    __shared__ int s_off;
    int tid = threadIdx.x;
    int bid = blockIdx.x;

    if (tid < 128) {
        int v2 = (tid < bid) ? g_bsum[tid] : 0;
#pragma unroll
        for (int m = 16; m > 0; m >>= 1)
            v2 += __shfl_xor_sync(0xffffffffu, v2, m);
        if ((tid & 31) == 0) ws[tid >> 5] = v2;
    }
    __syncthreads();
    if (tid == 0) s_off = ws[0] + ws[1] + ws[2] + ws[3];

    int i = bid * 1024 + tid;
    int v = (i < N) ? g_deg[i] : 0;
    sm[tid] = v;
    __syncthreads();
    for (int off = 1; off < 1024; off <<= 1) {
        int t = (tid >= off) ? sm[tid - off] : 0;
        __syncthreads();
        sm[tid] += t;
        __syncthreads();
    }
    if (i < N) {
        int excl = s_off + sm[tid] - v;
        g_row[i] = excl;
        g_cur[i] = excl;
    }
    if (bid == gridDim.x - 1 && tid == 0) g_row[N] = M;
}

__global__ void k_scatter(const void* __restrict__ ei, int E, int M)
{
    int i = blockIdx.x * blockDim.x + threadIdx.x;
    if (i >= M) return;
    int is32 = g_is32;
    int s, d;
    if (i < E) { s = edge_at(ei, i, is32); d = edge_at(ei, E + i, is32); }
    else       { s = d = i - E; }
    int pos = atomicAdd(&g_cur[d], 1);
    g_csr[pos] = s;
}

// ---- layer-1 gather: 8 lanes/node, single pass, 4-edge software pipeline --
__global__ __launch_bounds__(256) void k_gather1(const float* __restrict__ b1, int N)
{
    int t = blockIdx.x * 256 + threadIdx.x;
    int n = t >> 3, h = t & 7;
    if (n >= N) return;
    int beg = g_row[n], end = g_row[n + 1];
    float ad = g_a1d[n * 8 + h];
    const int ho = h * 8;

    float ssum = 0.f;
    float A[8] = {0.f, 0.f, 0.f, 0.f, 0.f, 0.f, 0.f, 0.f};

    int e = beg;
    for (; e + 4 <= end; e += 4) {
        // batch 4 edges: issue all loads up front for MLP
        int s0 = g_csr[e], s1 = g_csr[e + 1], s2 = g_csr[e + 2], s3 = g_csr[e + 3];
        float v0 = g_a1s[s0 * 8 + h];
        float v1 = g_a1s[s1 * 8 + h];
        float v2 = g_a1s[s2 * 8 + h];
        float v3 = g_a1s[s3 * 8 + h];
        const float4* p0 = (const float4*)(g_h1 + (size_t)s0 * 64 + ho);
        const float4* p1 = (const float4*)(g_h1 + (size_t)s1 * 64 + ho);
        const float4* p2 = (const float4*)(g_h1 + (size_t)s2 * 64 + ho);
        const float4* p3 = (const float4*)(g_h1 + (size_t)s3 * 64 + ho);
        float4 q0a = p0[0], q0b = p0[1];
        float4 q1a = p1[0], q1b = p1[1];
        float4 q2a = p2[0], q2b = p2[1];
        float4 q3a = p3[0], q3b = p3[1];
        v0 += ad; v1 += ad; v2 += ad; v3 += ad;
        float w0 = ex2a(fmaxf(v0, 0.2f * v0));
        float w1 = ex2a(fmaxf(v1, 0.2f * v1));
        float w2 = ex2a(fmaxf(v2, 0.2f * v2));
        float w3 = ex2a(fmaxf(v3, 0.2f * v3));
        ssum += w0 + w1 + w2 + w3;
        A[0] += w0 * q0a.x; A[1] += w0 * q0a.y; A[2] += w0 * q0a.z; A[3] += w0 * q0a.w;
        A[4] += w0 * q0b.x; A[5] += w0 * q0b.y; A[6] += w0 * q0b.z; A[7] += w0 * q0b.w;
        A[0] += w1 * q1a.x; A[1] += w1 * q1a.y; A[2] += w1 * q1a.z; A[3] += w1 * q1a.w;
        A[4] += w1 * q1b.x; A[5] += w1 * q1b.y; A[6] += w1 * q1b.z; A[7] += w1 * q1b.w;
        A[0] += w2 * q2a.x; A[1] += w2 * q2a.y; A[2] += w2 * q2a.z; A[3] += w2 * q2a.w;
        A[4] += w2 * q2b.x; A[5] += w2 * q2b.y; A[6] += w2 * q2b.z; A[7] += w2 * q2b.w;
        A[0] += w3 * q3a.x; A[1] += w3 * q3a.y; A[2] += w3 * q3a.z; A[3] += w3 * q3a.w;
        A[4] += w3 * q3b.x; A[5] += w3 * q3b.y; A[6] += w3 * q3b.z; A[7] += w3 * q3b.w;
    }
    for (; e < end; e++) {
        int s = g_csr[e];
        float v = g_a1s[s * 8 + h] + ad;
        float w = ex2a(fmaxf(v, 0.2f * v));
        ssum += w;
        const float4* hp = (const float4*)(g_h1 + (size_t)s * 64 + ho);
        float4 qa = hp[0], qb = hp[1];
        A[0] += w * qa.x; A[1] += w * qa.y; A[2] += w * qa.z; A[3] += w * qa.w;
        A[4] += w * qb.x; A[5] += w * qb.y; A[6] += w * qb.z; A[7] += w * qb.w;
    }

    float inv = 1.f / (ssum + 1e-16f);
    const float4* b4 = (const float4*)b1;
    float4 bb0 = b4[h * 2], bb1 = b4[h * 2 + 1];
    float4 r0, r1;
    r0.x = elu1(A[0] * inv + bb0.x); r0.y = elu1(A[1] * inv + bb0.y);
    r0.z = elu1(A[2] * inv + bb0.z); r0.w = elu1(A[3] * inv + bb0.w);
    r1.x = elu1(A[4] * inv + bb1.x); r1.y = elu1(A[5] * inv + bb1.y);
    r1.z = elu1(A[6] * inv + bb1.z); r1.w = elu1(A[7] * inv + bb1.w);
    float* op = g_hm + (size_t)n * 64 + ho;
    ((float4*)op)[0] = r0;
    ((float4*)op)[1] = r1;
}

// ---------------- GEMM2: h2 = hm @ W2 (+ scaled att-dot epilogue) ----------
__global__ __launch_bounds__(256) void k_gemm2(
    const float* __restrict__ W2, const float* __restrict__ as2,
    const float* __restrict__ ad2, int N)
{
    __shared__ __align__(16) float Ws[64][40];
    __shared__ __align__(16) float xsT[16][260];
    __shared__ float sA[40], sD[40];

    int tid = threadIdx.x;
    if (tid < 40) { sA[tid] = as2[tid] * LOG2E; sD[tid] = ad2[tid] * LOG2E; }
    for (int f = tid; f < 640; f += 256)
        ((float4*)&Ws[0][0])[f] = ((const float4*)W2)[f];

    int rg = tid >> 2;   // 0..63
    int cg = tid & 3;    // 0..3
    int rowBase = blockIdx.x * 256;

    u64 acc[4][5];
#pragma unroll
    for (int i = 0; i < 4; i++)
#pragma unroll
        for (int c = 0; c < 5; c++) acc[i][c] = 0ull;

    const float4* hm4 = (const float4*)g_hm;

    for (int kc = 0; kc < 4; kc++) {
        __syncthreads();
#pragma unroll
        for (int i = 0; i < 4; i++) {
            int f = tid + i * 256;
            int r = f >> 2, q = f & 3;
            int gr = rowBase + r;
            float4 xv = make_float4(0.f, 0.f, 0.f, 0.f);
            if (gr < N) xv = hm4[(size_t)gr * 16 + kc * 4 + q];
            xsT[q * 4 + 0][r] = xv.x;
            xsT[q * 4 + 1][r] = xv.y;
            xsT[q * 4 + 2][r] = xv.z;
            xsT[q * 4 + 3][r] = xv.w;
        }
        __syncthreads();
#pragma unroll
        for (int kk = 0; kk < 16; kk++) {
            float4 xv = *(const float4*)&xsT[kk][rg * 4];
            const u64* wp = (const u64*)&Ws[kc * 16 + kk][cg * 10];
            u64 w0 = wp[0], w1 = wp[1], w2 = wp[2], w3 = wp[3], w4 = wp[4];
            u64 xd[4] = {dup2(xv.x), dup2(xv.y), dup2(xv.z), dup2(xv.w)};
#pragma unroll
            for (int i = 0; i < 4; i++) {
                fma2(acc[i][0], xd[i], w0);
                fma2(acc[i][1], xd[i], w1);
                fma2(acc[i][2], xd[i], w2);
                fma2(acc[i][3], xd[i], w3);
                fma2(acc[i][4], xd[i], w4);
            }
        }
    }

#pragma unroll
    for (int i = 0; i < 4; i++) {
        int row = rowBase + rg * 4 + i;
        float o[10];
#pragma unroll
        for (int c = 0; c < 5; c++) {
            float2 v = un2(acc[i][c]);
            o[2 * c] = v.x; o[2 * c + 1] = v.y;
        }
        float ps = 0.f, pd = 0.f;
#pragma unroll
        for (int c = 0; c < 10; c++) {
            ps += o[c] * sA[cg * 10 + c];
            pd += o[c] * sD[cg * 10 + c];
        }
        ps += __shfl_xor_sync(0xffffffffu, ps, 1);
        ps += __shfl_xor_sync(0xffffffffu, ps, 2);
        pd += __shfl_xor_sync(0xffffffffu, pd, 1);
        pd += __shfl_xor_sync(0xffffffffu, pd, 2);
        if (row < N) {
            u64* hp = (u64*)(g_h2 + (size_t)row * 40 + cg * 10);
#pragma unroll
            for (int c = 0; c < 5; c++) hp[c] = acc[i][c];
            if (cg == 0) { g_a2s[row] = ps; g_a2d[row] = pd; }
        }
    }
}

// ---- layer-2 gather: 8 lanes/node, strided classes {p,p+8,..}, pipelined --
__global__ __launch_bounds__(256) void k_gather2(
    const float* __restrict__ b2, float* __restrict__ out, int N)
{
    int t = blockIdx.x * 256 + threadIdx.x;
    int n = t >> 3, p = t & 7;
    bool valid = (n < N);
    if (!valid) n = N - 1;              // keep lanes alive for shfl
    int beg = g_row[n], end = g_row[n + 1];
    float ad = g_a2d[n];

    float ssum = 0.f;
    float A[5] = {0.f, 0.f, 0.f, 0.f, 0.f};

    int e = beg;
    for (; e + 4 <= end; e += 4) {
        int s0 = g_csr[e], s1 = g_csr[e + 1], s2 = g_csr[e + 2], s3 = g_csr[e + 3];
        float v0 = g_a2s[s0], v1 = g_a2s[s1], v2 = g_a2s[s2], v3 = g_a2s[s3];
        const float* h0 = g_h2 + (size_t)s0 * 40 + p;
        const float* h1p = g_h2 + (size_t)s1 * 40 + p;
        const float* h2p = g_h2 + (size_t)s2 * 40 + p;
        const float* h3 = g_h2 + (size_t)s3 * 40 + p;
        float q0[5], q1[5], q2[5], q3[5];
#pragma unroll
        for (int j = 0; j < 5; j++) { q0[j] = h0[j * 8]; q1[j] = h1p[j * 8]; q2[j] = h2p[j * 8]; q3[j] = h3[j * 8]; }
        v0 += ad; v1 += ad; v2 += ad; v3 += ad;
        float w0 = ex2a(fmaxf(v0, 0.2f * v0));
        float w1 = ex2a(fmaxf(v1, 0.2f * v1));
        float w2 = ex2a(fmaxf(v2, 0.2f * v2));
        float w3 = ex2a(fmaxf(v3, 0.2f * v3));
        ssum += w0 + w1 + w2 + w3;
#pragma unroll
        for (int j = 0; j < 5; j++)
            A[j] += w0 * q0[j] + w1 * q1[j] + w2 * q2[j] + w3 * q3[j];
    }
    for (; e < end; e++) {
        int s = g_csr[e];
        float v = g_a2s[s] + ad;
        float w = ex2a(fmaxf(v, 0.2f * v));
        ssum += w;
        const float* hp = g_h2 + (size_t)s * 40 + p;
#pragma unroll
        for (int j = 0; j < 5; j++) A[j] += w * hp[j * 8];
    }
    float inv = 1.f / (ssum + 1e-16f);

    float o[5];
    float mx = -1e30f;
#pragma unroll
    for (int j = 0; j < 5; j++) {
        o[j] = A[j] * inv + b2[p + j * 8];
        mx = fmaxf(mx, o[j]);
    }
    mx = fmaxf(mx, __shfl_xor_sync(0xffffffffu, mx, 1));
    mx = fmaxf(mx, __shfl_xor_sync(0xffffffffu, mx, 2));
    mx = fmaxf(mx, __shfl_xor_sync(0xffffffffu, mx, 4));
    float se = 0.f;
#pragma unroll
    for (int j = 0; j < 5; j++) se += __expf(o[j] - mx);
    se += __shfl_xor_sync(0xffffffffu, se, 1);
    se += __shfl_xor_sync(0xffffffffu, se, 2);
    se += __shfl_xor_sync(0xffffffffu, se, 4);
    float lse = mx + logf(se);

    if (valid) {
        float* op = out + (size_t)n * 40 + p;
#pragma unroll
        for (int j = 0; j < 5; j++) op[j * 8] = o[j] - lse;
    }
}

// ---------------- launch ----------------
extern "C" void kernel_launch(void* const* d_in, const int* in_sizes, int n_in,
                              void* d_out, int out_size)
{
    const float* x    = (const float*)d_in[0];
    const void*  ei   = d_in[1];
    const float* W1   = (const float*)d_in[2];
    const float* as1  = (const float*)d_in[3];
    const float* ad1  = (const float*)d_in[4];
    const float* b1   = (const float*)d_in[5];
    const float* W2   = (const float*)d_in[6];
    const float* as2  = (const float*)d_in[7];
    const float* ad2  = (const float*)d_in[8];
    const float* b2   = (const float*)d_in[9];
    float*       out  = (float*)d_out;

    int N = in_sizes[0] / F_IN;
    int E = in_sizes[1] / 2;
    int M = E + N;
    int NB = (N + 1023) / 1024;

    static cudaStream_t s_side = nullptr;
    static cudaEvent_t  ev_fork = nullptr, ev_join = nullptr;
    if (!s_side) {
        cudaStreamCreateWithFlags(&s_side, cudaStreamNonBlocking);
        cudaEventCreateWithFlags(&ev_fork, cudaEventDisableTiming);
        cudaEventCreateWithFlags(&ev_join, cudaEventDisableTiming);
    }

    // fork: gemm1 on side stream, concurrent with CSR build
    cudaEventRecord(ev_fork, 0);
    cudaStreamWaitEvent(s_side, ev_fork, 0);
    k_gemm1<<<(N + 127) / 128, 256, 0, s_side>>>(x, W1, as1, ad1, N);
    cudaEventRecord(ev_join, s_side);

    // main chain: CSR build
    k_init<<<(N + 255) / 256, 256>>>(ei, N);
    k_deg<<<(M + 255) / 256, 256>>>(ei, E, M);
    k_bsum<<<NB, 1024>>>(N);
    k_scan3<<<NB, 1024>>>(N, M);
    k_scatter<<<(M + 255) / 256, 256>>>(ei, E, M);

    // join, then attention layers
    cudaStreamWaitEvent(0, ev_join, 0);
    k_gather1<<<(N * 8 + 255) / 256, 256>>>(b1, N);
    k_gemm2<<<(N + 255) / 256, 256>>>(W2, as2, ad2, N);
    k_gather2<<<(N * 8 + 255) / 256, 256>>>(b2, out, N);
}

// round 6
// speedup vs baseline: 1.1848x; 1.0674x over previous
#include <cuda_runtime.h>
#include <stdint.h>

#define F_IN 128
#define D1   64
#define H1   8
#define C2   40
#define NMAX 100352
#define MMAX 1703936   // E + N upper bound
#define LOG2E 1.44269504088896f

#define FLAG_AGG (1 << 28)
#define FLAG_PRE (1 << 29)
#define VMASK    ((1 << 24) - 1)

typedef unsigned long long u64;

// ---------------- scratch (static device allocations; zero-initialized) ----
__device__ __align__(16) float g_h1 [NMAX * D1];
__device__ __align__(16) float g_hm [NMAX * D1];
__device__ __align__(16) float g_a1s[NMAX * H1];
__device__ __align__(16) float g_a1d[NMAX * H1];
__device__ __align__(16) float g_h2 [NMAX * C2];
__device__ __align__(16) float g_a2s[NMAX];
__device__ __align__(16) float g_a2d[NMAX];
__device__ __align__(16) int   g_deg[NMAX];     // zeroed by k_scatter tail each call
__device__ __align__(16) int   g_cur[NMAX];
__device__ __align__(16) int   g_row[NMAX + 1];
__device__ __align__(16) int   g_stat[256];     // lookback statuses; zeroed by k_scatter tail
__device__ __align__(16) int   g_csr[MMAX];

// ---------------- helpers ----------------
__device__ __forceinline__ float elu1(float v)  { return v > 0.f ? v : (__expf(v) - 1.f); }
__device__ __forceinline__ float ex2a(float x)  { float r; asm("ex2.approx.ftz.f32 %0,%1;" : "=f"(r) : "f"(x)); return r; }
__device__ __forceinline__ u64  dup2(float x)   { u64 r; asm("mov.b64 %0,{%1,%1};" : "=l"(r) : "f"(x)); return r; }
__device__ __forceinline__ void fma2(u64& d, u64 a, u64 b) { asm("fma.rn.f32x2 %0,%1,%2,%0;" : "+l"(d) : "l"(a), "l"(b)); }
__device__ __forceinline__ float2 un2(u64 v)    { float2 f; asm("mov.b64 {%0,%1},%2;" : "=f"(f.x), "=f"(f.y) : "l"(v)); return f; }

__device__ __forceinline__ int edge_at(const void* ei, int idx, int is32)
{
    return is32 ? ((const int*)ei)[idx] : (int)((const long long*)ei)[idx];
}

// per-block edge-dtype detect: first 64 int64 values all in [0,N) => int64.
__device__ __forceinline__ int detect_is32(const void* ei, int N)
{
    __shared__ int s_is32;
    if (threadIdx.x < 32) {
        const long long* p = (const long long*)ei;
        long long v0 = p[threadIdx.x];
        long long v1 = p[threadIdx.x + 32];
        int bad = (v0 < 0 || v0 >= (long long)N) || (v1 < 0 || v1 >= (long long)N);
        unsigned m = __ballot_sync(0xffffffffu, bad);
        if (threadIdx.x == 0) s_is32 = (m != 0);
    }
    __syncthreads();
    return s_is32;
}

// ---------------- GEMM1: h1 = x @ W1  (+ scaled att-dot epilogue) ----------
__global__ __launch_bounds__(256) void k_gemm1(
    const float* __restrict__ x, const float* __restrict__ W,
    const float* __restrict__ atts, const float* __restrict__ attd, int N)
{
    __shared__ __align__(16) float Ws[32][64];
    __shared__ __align__(16) float xsT[32][132];
    __shared__ float sAs[64], sAd[64];

    int tid = threadIdx.x;
    if (tid < 64) { sAs[tid] = atts[tid] * LOG2E; sAd[tid] = attd[tid] * LOG2E; }

    int rg = tid >> 3;        // 0..31
    int cg = tid & 7;         // 0..7
    int rowBase = blockIdx.x * 128;

    u64 acc[4][4];
#pragma unroll
    for (int i = 0; i < 4; i++)
#pragma unroll
        for (int c = 0; c < 4; c++) acc[i][c] = 0ull;

    const float4* x4 = (const float4*)x;
    const float4* W4 = (const float4*)W;

    for (int kc = 0; kc < 4; kc++) {
        __syncthreads();
#pragma unroll
        for (int i = 0; i < 2; i++) {
            int f = tid + i * 256;
            int kk = f >> 4, qj = f & 15;
            ((float4*)&Ws[kk][0])[qj] = W4[(kc * 32 + kk) * 16 + qj];
        }
#pragma unroll
        for (int i = 0; i < 4; i++) {
            int f = tid + i * 256;
            int r = f >> 3, q = f & 7;
            int gr = rowBase + r;
            float4 xv = make_float4(0.f, 0.f, 0.f, 0.f);
            if (gr < N) xv = x4[(size_t)gr * 32 + kc * 8 + q];
            xsT[q * 4 + 0][r] = xv.x;
            xsT[q * 4 + 1][r] = xv.y;
            xsT[q * 4 + 2][r] = xv.z;
            xsT[q * 4 + 3][r] = xv.w;
        }
        __syncthreads();
#pragma unroll
        for (int kk = 0; kk < 32; kk++) {
            float4 xv = *(const float4*)&xsT[kk][rg * 4];
            ulonglong2 wA = *(const ulonglong2*)&Ws[kk][cg * 8];
            ulonglong2 wB = *(const ulonglong2*)&Ws[kk][cg * 8 + 4];
            u64 xd[4] = {dup2(xv.x), dup2(xv.y), dup2(xv.z), dup2(xv.w)};
#pragma unroll
            for (int i = 0; i < 4; i++) {
                fma2(acc[i][0], xd[i], wA.x);
                fma2(acc[i][1], xd[i], wA.y);
                fma2(acc[i][2], xd[i], wB.x);
                fma2(acc[i][3], xd[i], wB.y);
            }
        }
    }

#pragma unroll
    for (int i = 0; i < 4; i++) {
        int row = rowBase + rg * 4 + i;
        if (row >= N) continue;
        float o[8];
#pragma unroll
        for (int c = 0; c < 4; c++) {
            float2 v = un2(acc[i][c]);
            o[2 * c] = v.x; o[2 * c + 1] = v.y;
        }
        float* hp = g_h1 + (size_t)row * 64 + cg * 8;
        ((float4*)hp)[0] = make_float4(o[0], o[1], o[2], o[3]);
        ((float4*)hp)[1] = make_float4(o[4], o[5], o[6], o[7]);
        float s = 0.f, d = 0.f;
#pragma unroll
        for (int c = 0; c < 8; c++) {
            s += o[c] * sAs[cg * 8 + c];
            d += o[c] * sAd[cg * 8 + c];
        }
        g_a1s[row * 8 + cg] = s;
        g_a1d[row * 8 + cg] = d;
    }
}

// ---------------- k_deg: count in-degree over real edges only --------------
__global__ __launch_bounds__(256) void k_deg(const void* __restrict__ ei, int E, int N)
{
    int is32 = detect_is32(ei, N);
    int i = blockIdx.x * blockDim.x + threadIdx.x;
    if (i >= E) return;
    atomicAdd(&g_deg[E > 0 ? edge_at(ei, E + i, is32) : 0], 1);
}

// ---------------- single-kernel scan with decoupled lookback ---------------
// input: g_deg[i] (+1 self-loop per node). output: g_row, g_cur exclusive
// prefix. status in g_stat (zero = invalid; bit28 = aggregate; bit29 = prefix)
__global__ __launch_bounds__(1024) void k_scan(int N, int M)
{
    __shared__ int sWarp[32];
    __shared__ int s_exc;
    int tid  = threadIdx.x;
    int lane = tid & 31;
    int wid  = tid >> 5;
    int bid  = blockIdx.x;
    int i = bid * 1024 + tid;

    int v = (i < N) ? (g_deg[i] + 1) : 0;   // +1 = self loop

    // warp inclusive scan
    int x = v;
#pragma unroll
    for (int d = 1; d < 32; d <<= 1) {
        int y = __shfl_up_sync(0xffffffffu, x, d);
        if (lane >= d) x += y;
    }
    if (lane == 31) sWarp[wid] = x;
    __syncthreads();
    if (wid == 0) {
        int t = sWarp[lane];
#pragma unroll
        for (int d = 1; d < 32; d <<= 1) {
            int y = __shfl_up_sync(0xffffffffu, t, d);
            if (lane >= d) t += y;
        }
        sWarp[lane] = t;
    }
    __syncthreads();
    int incl = x + (wid ? sWarp[wid - 1] : 0);
    int blockTotal = sWarp[31];

    // publish aggregate ASAP (block 0 publishes final prefix directly)
    if (tid == 0) {
        if (bid == 0) {
            atomicExch(&g_stat[0], FLAG_PRE | blockTotal);
            s_exc = 0;
        } else {
            atomicExch(&g_stat[bid], FLAG_AGG | blockTotal);
        }
    }

    // warp 0: windowed lookback
    if (bid > 0 && wid == 0) {
        int run = 0, base = bid;
        for (;;) {
            int j = base - 1 - lane;
            int sv;
            if (j >= 0) {
                do { sv = atomicAdd(&g_stat[j], 0); } while (sv == 0);
            } else {
                sv = FLAG_PRE;   // virtual block with prefix 0
            }
            __syncwarp();
            unsigned pm = __ballot_sync(0xffffffffu, (sv & FLAG_PRE) != 0);
            if (pm) {
                int lp = __ffs(pm) - 1;        // closest predecessor with prefix
                if (lane <= lp) run += sv & VMASK;
                break;
            }
            run += sv & VMASK;
            base -= 32;
        }
#pragma unroll
        for (int m = 16; m > 0; m >>= 1)
            run += __shfl_xor_sync(0xffffffffu, run, m);
        if (lane == 0) {
            s_exc = run;
            atomicExch(&g_stat[bid], FLAG_PRE | (run + blockTotal));
        }
    }
    __syncthreads();

    if (i < N) {
        int excl = s_exc + incl - v;
        g_row[i] = excl;
        g_cur[i] = excl;
    }
    if (bid == gridDim.x - 1 && tid == 0) g_row[N] = M;
}

// ---------------- k_scatter: fill CSR, then reset deg/status for next call -
__global__ __launch_bounds__(256) void k_scatter(const void* __restrict__ ei, int E, int M, int N)
{
    int is32 = detect_is32(ei, N);
    int i = blockIdx.x * blockDim.x + threadIdx.x;
    if (i < M) {
        int s, d;
        if (i < E) { s = edge_at(ei, i, is32); d = edge_at(ei, E + i, is32); }
        else       { s = d = i - E; }
        g_csr[atomicAdd(&g_cur[d], 1)] = s;
    }
    // reset state for the next launch (g_deg / g_stat unused by this kernel)
    if (i < N)   g_deg[i] = 0;
    if (i < 256) g_stat[i] = 0;
}

// ---- layer-1 gather: 8 lanes/node, single pass, simple rolled loop --------
__global__ __launch_bounds__(256) void k_gather1(const float* __restrict__ b1, int N)
{
    int t = blockIdx.x * 256 + threadIdx.x;
    int n = t >> 3, h = t & 7;
    if (n >= N) return;
    int beg = g_row[n], end = g_row[n + 1];
    float ad = g_a1d[n * 8 + h];
    const int ho = h * 8;

    float ssum = 0.f;
    float4 A0 = make_float4(0.f, 0.f, 0.f, 0.f), A1 = A0;
    for (int e = beg; e < end; e++) {
        int s = g_csr[e];
        float v = g_a1s[s * 8 + h] + ad;
        float w = ex2a(fmaxf(v, 0.2f * v));
        ssum += w;
        const float4* hp = (const float4*)(g_h1 + (size_t)s * 64 + ho);
        float4 u0 = hp[0], u1 = hp[1];
        A0.x += w * u0.x; A0.y += w * u0.y; A0.z += w * u0.z; A0.w += w * u0.w;
        A1.x += w * u1.x; A1.y += w * u1.y; A1.z += w * u1.z; A1.w += w * u1.w;
    }
    float inv = 1.f / (ssum + 1e-16f);
    const float4* b4 = (const float4*)b1;
    float4 bb0 = b4[h * 2], bb1 = b4[h * 2 + 1];
    float4 r0, r1;
    r0.x = elu1(A0.x * inv + bb0.x); r0.y = elu1(A0.y * inv + bb0.y);
    r0.z = elu1(A0.z * inv + bb0.z); r0.w = elu1(A0.w * inv + bb0.w);
    r1.x = elu1(A1.x * inv + bb1.x); r1.y = elu1(A1.y * inv + bb1.y);
    r1.z = elu1(A1.z * inv + bb1.z); r1.w = elu1(A1.w * inv + bb1.w);
    float* op = g_hm + (size_t)n * 64 + ho;
    ((float4*)op)[0] = r0;
    ((float4*)op)[1] = r1;
}

// ---------------- GEMM2: h2 = hm @ W2 (+ scaled att-dot epilogue) ----------
__global__ __launch_bounds__(256) void k_gemm2(
    const float* __restrict__ W2, const float* __restrict__ as2,
    const float* __restrict__ ad2, int N)
{
    __shared__ __align__(16) float Ws[64][40];
    __shared__ __align__(16) float xsT[16][260];
    __shared__ float sA[40], sD[40];

    int tid = threadIdx.x;
    if (tid < 40) { sA[tid] = as2[tid] * LOG2E; sD[tid] = ad2[tid] * LOG2E; }
    for (int f = tid; f < 640; f += 256)
        ((float4*)&Ws[0][0])[f] = ((const float4*)W2)[f];

    int rg = tid >> 2;   // 0..63
    int cg = tid & 3;    // 0..3
    int rowBase = blockIdx.x * 256;

    u64 acc[4][5];
#pragma unroll
    for (int i = 0; i < 4; i++)
#pragma unroll
        for (int c = 0; c < 5; c++) acc[i][c] = 0ull;

    const float4* hm4 = (const float4*)g_hm;

    for (int kc = 0; kc < 4; kc++) {
        __syncthreads();
#pragma unroll
        for (int i = 0; i < 4; i++) {
            int f = tid + i * 256;
            int r = f >> 2, q = f & 3;
            int gr = rowBase + r;
            float4 xv = make_float4(0.f, 0.f, 0.f, 0.f);
            if (gr < N) xv = hm4[(size_t)gr * 16 + kc * 4 + q];
            xsT[q * 4 + 0][r] = xv.x;
            xsT[q * 4 + 1][r] = xv.y;
            xsT[q * 4 + 2][r] = xv.z;
            xsT[q * 4 + 3][r] = xv.w;
        }
        __syncthreads();
#pragma unroll
        for (int kk = 0; kk < 16; kk++) {
            float4 xv = *(const float4*)&xsT[kk][rg * 4];
            const u64* wp = (const u64*)&Ws[kc * 16 + kk][cg * 10];
            u64 w0 = wp[0], w1 = wp[1], w2 = wp[2], w3 = wp[3], w4 = wp[4];
            u64 xd[4] = {dup2(xv.x), dup2(xv.y), dup2(xv.z), dup2(xv.w)};
#pragma unroll
            for (int i = 0; i < 4; i++) {
                fma2(acc[i][0], xd[i], w0);
                fma2(acc[i][1], xd[i], w1);
                fma2(acc[i][2], xd[i], w2);
                fma2(acc[i][3], xd[i], w3);
                fma2(acc[i][4], xd[i], w4);
            }
        }
    }

#pragma unroll
    for (int i = 0; i < 4; i++) {
        int row = rowBase + rg * 4 + i;
        float o[10];
#pragma unroll
        for (int c = 0; c < 5; c++) {
            float2 v = un2(acc[i][c]);
            o[2 * c] = v.x; o[2 * c + 1] = v.y;
        }
        float ps = 0.f, pd = 0.f;
#pragma unroll
        for (int c = 0; c < 10; c++) {
            ps += o[c] * sA[cg * 10 + c];
            pd += o[c] * sD[cg * 10 + c];
        }
        ps += __shfl_xor_sync(0xffffffffu, ps, 1);
        ps += __shfl_xor_sync(0xffffffffu, ps, 2);
        pd += __shfl_xor_sync(0xffffffffu, pd, 1);
        pd += __shfl_xor_sync(0xffffffffu, pd, 2);
        if (row < N) {
            u64* hp = (u64*)(g_h2 + (size_t)row * 40 + cg * 10);
#pragma unroll
            for (int c = 0; c < 5; c++) hp[c] = acc[i][c];
            if (cg == 0) { g_a2s[row] = ps; g_a2d[row] = pd; }
        }
    }
}

// ---- layer-2 gather: 8 lanes/node, 5 contiguous classes/lane --------------
__global__ __launch_bounds__(256) void k_gather2(
    const float* __restrict__ b2, float* __restrict__ out, int N)
{
    int t = blockIdx.x * 256 + threadIdx.x;
    int n = t >> 3, p = t & 7;
    bool valid = (n < N);
    if (!valid) n = N - 1;              // keep lanes alive for shfl
    int beg = g_row[n], end = g_row[n + 1];
    float ad = g_a2d[n];

    float ssum = 0.f;
    float acc[5] = {0.f, 0.f, 0.f, 0.f, 0.f};
    for (int e = beg; e < end; e++) {
        int s = g_csr[e];
        float v = g_a2s[s] + ad;
        float w = ex2a(fmaxf(v, 0.2f * v));
        ssum += w;
        const float* hp = g_h2 + (size_t)s * 40 + p * 5;
#pragma unroll
        for (int j = 0; j < 5; j++) acc[j] += w * hp[j];
    }
    float inv = 1.f / (ssum + 1e-16f);

    float o[5];
    float mx = -1e30f;
#pragma unroll
    for (int j = 0; j < 5; j++) { o[j] = acc[j] * inv + b2[p * 5 + j]; mx = fmaxf(mx, o[j]); }
#pragma unroll
    for (int msk = 1; msk < 8; msk <<= 1)
        mx = fmaxf(mx, __shfl_xor_sync(0xffffffffu, mx, msk));
    float se = 0.f;
#pragma unroll
    for (int j = 0; j < 5; j++) se += __expf(o[j] - mx);
#pragma unroll
    for (int msk = 1; msk < 8; msk <<= 1)
        se += __shfl_xor_sync(0xffffffffu, se, msk);
    float lse = mx + logf(se);

    if (valid) {
        float* op = out + (size_t)n * 40 + p * 5;
#pragma unroll
        for (int j = 0; j < 5; j++) op[j] = o[j] - lse;
    }
}

// ---------------- launch ----------------
extern "C" void kernel_launch(void* const* d_in, const int* in_sizes, int n_in,
                              void* d_out, int out_size)
{
    const float* x    = (const float*)d_in[0];
    const void*  ei   = d_in[1];
    const float* W1   = (const float*)d_in[2];
    const float* as1  = (const float*)d_in[3];
    const float* ad1  = (const float*)d_in[4];
    const float* b1   = (const float*)d_in[5];
    const float* W2   = (const float*)d_in[6];
    const float* as2  = (const float*)d_in[7];
    const float* ad2  = (const float*)d_in[8];
    const float* b2   = (const float*)d_in[9];
    float*       out  = (float*)d_out;

    int N = in_sizes[0] / F_IN;
    int E = in_sizes[1] / 2;
    int M = E + N;
    int NB = (N + 1023) / 1024;

    static cudaStream_t s_side = nullptr;
    static cudaEvent_t  ev_fork = nullptr, ev_join = nullptr;
    if (!s_side) {
        cudaStreamCreateWithFlags(&s_side, cudaStreamNonBlocking);
        cudaEventCreateWithFlags(&ev_fork, cudaEventDisableTiming);
        cudaEventCreateWithFlags(&ev_join, cudaEventDisableTiming);
    }

    // fork: gemm1 on side stream, concurrent with CSR build
    cudaEventRecord(ev_fork, 0);
    cudaStreamWaitEvent(s_side, ev_fork, 0);
    k_gemm1<<<(N + 127) / 128, 256, 0, s_side>>>(x, W1, as1, ad1, N);
    cudaEventRecord(ev_join, s_side);

    // main chain: CSR build (deg -> lookback-scan -> scatter)
    k_deg<<<(E + 255) / 256, 256>>>(ei, E, N);
    k_scan<<<NB, 1024>>>(N, M);
    k_scatter<<<(M + 255) / 256, 256>>>(ei, E, M, N);

    // join, then attention layers
    cudaStreamWaitEvent(0, ev_join, 0);
    k_gather1<<<(N * 8 + 255) / 256, 256>>>(b1, N);
    k_gemm2<<<(N + 255) / 256, 256>>>(W2, as2, ad2, N);
    k_gather2<<<(N * 8 + 255) / 256, 256>>>(b2, out, N);
}

// round 7
// speedup vs baseline: 1.3130x; 1.1082x over previous
#include <cuda_runtime.h>
#include <cuda_fp16.h>
#include <stdint.h>

#define F_IN 128
#define D1   64
#define H1   8
#define C2   40
#define NMAX 100352
#define MMAX 1703936   // E + N upper bound
#define LOG2E 1.44269504088896f

#define FLAG_AGG (1 << 28)
#define FLAG_PRE (1 << 29)
#define VMASK    ((1 << 24) - 1)

typedef unsigned long long u64;

// ---------------- scratch (static device allocations; zero-initialized) ----
__device__ __align__(16) __half g_h1h[NMAX * D1];   // layer1 features (fp16)
__device__ __align__(16) float  g_hm [NMAX * D1];   // layer2 input (fp32)
__device__ __align__(16) float  g_a1s[NMAX * H1];
__device__ __align__(16) float  g_a1d[NMAX * H1];
__device__ __align__(16) __half g_h2h[NMAX * C2];   // layer2 features (fp16)
__device__ __align__(16) float  g_a2s[NMAX];
__device__ __align__(16) float  g_a2d[NMAX];
__device__ __align__(16) int    g_deg[NMAX];        // zeroed by k_scatter tail
__device__ __align__(16) int    g_row[NMAX + 1];
__device__ __align__(16) int    g_stat[256];        // lookback statuses; zeroed by k_scatter tail
__device__ __align__(16) int    g_rank[MMAX];
__device__ __align__(16) int    g_csr[MMAX];

// ---------------- helpers ----------------
__device__ __forceinline__ float elu1(float v)  { return v > 0.f ? v : (__expf(v) - 1.f); }
__device__ __forceinline__ float ex2a(float x)  { float r; asm("ex2.approx.ftz.f32 %0,%1;" : "=f"(r) : "f"(x)); return r; }
__device__ __forceinline__ u64  dup2(float x)   { u64 r; asm("mov.b64 %0,{%1,%1};" : "=l"(r) : "f"(x)); return r; }
__device__ __forceinline__ void fma2(u64& d, u64 a, u64 b) { asm("fma.rn.f32x2 %0,%1,%2,%0;" : "+l"(d) : "l"(a), "l"(b)); }
__device__ __forceinline__ float2 un2(u64 v)    { float2 f; asm("mov.b64 {%0,%1},%2;" : "=f"(f.x), "=f"(f.y) : "l"(v)); return f; }

__device__ __forceinline__ int edge_at(const void* ei, int idx, int is32)
{
    return is32 ? ((const int*)ei)[idx] : (int)((const long long*)ei)[idx];
}

// per-block edge-dtype detect: first 64 int64 values all in [0,N) => int64.
__device__ __forceinline__ int detect_is32(const void* ei, int N)
{
    __shared__ int s_is32;
    if (threadIdx.x < 32) {
        const long long* p = (const long long*)ei;
        long long v0 = p[threadIdx.x];
        long long v1 = p[threadIdx.x + 32];
        int bad = (v0 < 0 || v0 >= (long long)N) || (v1 < 0 || v1 >= (long long)N);
        unsigned m = __ballot_sync(0xffffffffu, bad);
        if (threadIdx.x == 0) s_is32 = (m != 0);
    }
    __syncthreads();
    return s_is32;
}

// ---------------- GEMM1: h1 = x @ W1  (+ scaled att-dot epilogue) ----------
__global__ __launch_bounds__(256) void k_gemm1(
    const float* __restrict__ x, const float* __restrict__ W,
    const float* __restrict__ atts, const float* __restrict__ attd, int N)
{
    __shared__ __align__(16) float Ws[32][64];
    __shared__ __align__(16) float xsT[32][132];
    __shared__ float sAs[64], sAd[64];

    int tid = threadIdx.x;
    if (tid < 64) { sAs[tid] = atts[tid] * LOG2E; sAd[tid] = attd[tid] * LOG2E; }

    int rg = tid >> 3;        // 0..31
    int cg = tid & 7;         // 0..7
    int rowBase = blockIdx.x * 128;

    u64 acc[4][4];
#pragma unroll
    for (int i = 0; i < 4; i++)
#pragma unroll
        for (int c = 0; c < 4; c++) acc[i][c] = 0ull;

    const float4* x4 = (const float4*)x;
    const float4* W4 = (const float4*)W;

    for (int kc = 0; kc < 4; kc++) {
        __syncthreads();
#pragma unroll
        for (int i = 0; i < 2; i++) {
            int f = tid + i * 256;
            int kk = f >> 4, qj = f & 15;
            ((float4*)&Ws[kk][0])[qj] = W4[(kc * 32 + kk) * 16 + qj];
        }
#pragma unroll
        for (int i = 0; i < 4; i++) {
            int f = tid + i * 256;
            int r = f >> 3, q = f & 7;
            int gr = rowBase + r;
            float4 xv = make_float4(0.f, 0.f, 0.f, 0.f);
            if (gr < N) xv = x4[(size_t)gr * 32 + kc * 8 + q];
            xsT[q * 4 + 0][r] = xv.x;
            xsT[q * 4 + 1][r] = xv.y;
            xsT[q * 4 + 2][r] = xv.z;
            xsT[q * 4 + 3][r] = xv.w;
        }
        __syncthreads();
#pragma unroll
        for (int kk = 0; kk < 32; kk++) {
            float4 xv = *(const float4*)&xsT[kk][rg * 4];
            ulonglong2 wA = *(const ulonglong2*)&Ws[kk][cg * 8];
            ulonglong2 wB = *(const ulonglong2*)&Ws[kk][cg * 8 + 4];
            u64 xd[4] = {dup2(xv.x), dup2(xv.y), dup2(xv.z), dup2(xv.w)};
#pragma unroll
            for (int i = 0; i < 4; i++) {
                fma2(acc[i][0], xd[i], wA.x);
                fma2(acc[i][1], xd[i], wA.y);
                fma2(acc[i][2], xd[i], wB.x);
                fma2(acc[i][3], xd[i], wB.y);
            }
        }
    }

#pragma unroll
    for (int i = 0; i < 4; i++) {
        int row = rowBase + rg * 4 + i;
        if (row >= N) continue;
        float o[8];
#pragma unroll
        for (int c = 0; c < 4; c++) {
            float2 v = un2(acc[i][c]);
            o[2 * c] = v.x; o[2 * c + 1] = v.y;
        }
        // store h1 as fp16 (8 halves = 16 B)
        union { uint4 u; __half2 h[4]; } pk;
#pragma unroll
        for (int c = 0; c < 4; c++)
            pk.h[c] = __floats2half2_rn(o[2 * c], o[2 * c + 1]);
        *(uint4*)(g_h1h + (size_t)row * 64 + cg * 8) = pk.u;

        float s = 0.f, d = 0.f;
#pragma unroll
        for (int c = 0; c < 8; c++) {
            s += o[c] * sAs[cg * 8 + c];
            d += o[c] * sAd[cg * 8 + c];
        }
        g_a1s[row * 8 + cg] = s;
        g_a1d[row * 8 + cg] = d;
    }
}

// ---------------- k_deg: count in-degree + record per-edge rank ------------
__global__ __launch_bounds__(256) void k_deg(const void* __restrict__ ei, int E, int N)
{
    int is32 = detect_is32(ei, N);
    int i = blockIdx.x * blockDim.x + threadIdx.x;
    if (i >= E) return;
    int d = edge_at(ei, E + i, is32);
    g_rank[i] = atomicAdd(&g_deg[d], 1);
}

// ---------------- single-kernel scan with decoupled lookback ---------------
__global__ __launch_bounds__(1024) void k_scan(int N, int M)
{
    __shared__ int sWarp[32];
    __shared__ int s_exc;
    int tid  = threadIdx.x;
    int lane = tid & 31;
    int wid  = tid >> 5;
    int bid  = blockIdx.x;
    int i = bid * 1024 + tid;

    int v = (i < N) ? (g_deg[i] + 1) : 0;   // +1 = self loop

    int x = v;
#pragma unroll
    for (int d = 1; d < 32; d <<= 1) {
        int y = __shfl_up_sync(0xffffffffu, x, d);
        if (lane >= d) x += y;
    }
    if (lane == 31) sWarp[wid] = x;
    __syncthreads();
    if (wid == 0) {
        int t = sWarp[lane];
#pragma unroll
        for (int d = 1; d < 32; d <<= 1) {
            int y = __shfl_up_sync(0xffffffffu, t, d);
            if (lane >= d) t += y;
        }
        sWarp[lane] = t;
    }
    __syncthreads();
    int incl = x + (wid ? sWarp[wid - 1] : 0);
    int blockTotal = sWarp[31];

    if (tid == 0) {
        if (bid == 0) {
            atomicExch(&g_stat[0], FLAG_PRE | blockTotal);
            s_exc = 0;
        } else {
            atomicExch(&g_stat[bid], FLAG_AGG | blockTotal);
        }
    }

    if (bid > 0 && wid == 0) {
        int run = 0, base = bid;
        for (;;) {
            int j = base - 1 - lane;
            int sv;
            if (j >= 0) {
                do { sv = atomicAdd(&g_stat[j], 0); } while (sv == 0);
            } else {
                sv = FLAG_PRE;
            }
            __syncwarp();
            unsigned pm = __ballot_sync(0xffffffffu, (sv & FLAG_PRE) != 0);
            if (pm) {
                int lp = __ffs(pm) - 1;
                if (lane <= lp) run += sv & VMASK;
                break;
            }
            run += sv & VMASK;
            base -= 32;
        }
#pragma unroll
        for (int m = 16; m > 0; m >>= 1)
            run += __shfl_xor_sync(0xffffffffu, run, m);
        if (lane == 0) {
            s_exc = run;
            atomicExch(&g_stat[bid], FLAG_PRE | (run + blockTotal));
        }
    }
    __syncthreads();

    if (i < N) g_row[i] = s_exc + incl - v;
    if (bid == gridDim.x - 1 && tid == 0) g_row[N] = M;
}

// ---------------- k_scatter: atomic-free CSR fill + state reset ------------
__global__ __launch_bounds__(256) void k_scatter(const void* __restrict__ ei, int E, int M, int N)
{
    int is32 = detect_is32(ei, N);
    int i = blockIdx.x * blockDim.x + threadIdx.x;
    if (i < M) {
        int s, slot;
        if (i < E) {
            s = edge_at(ei, i, is32);
            int d = edge_at(ei, E + i, is32);
            slot = g_row[d] + g_rank[i];
        } else {
            int n = i - E;
            s = n;
            slot = g_row[n + 1] - 1;   // self loop: last slot of bucket
        }
        g_csr[slot] = s;
    }
    // reset state for the next launch
    if (i < N)   g_deg[i] = 0;
    if (i < 256) g_stat[i] = 0;
}

// ---- layer-1 gather: 8 lanes/node, fp16 features, fp32 accumulate ---------
__global__ __launch_bounds__(256) void k_gather1(const float* __restrict__ b1, int N)
{
    int t = blockIdx.x * 256 + threadIdx.x;
    int n = t >> 3, h = t & 7;
    if (n >= N) return;
    int beg = g_row[n], end = g_row[n + 1];
    float ad = g_a1d[n * 8 + h];

    float ssum = 0.f;
    float4 A0 = make_float4(0.f, 0.f, 0.f, 0.f), A1 = A0;
    for (int e = beg; e < end; e++) {
        int s = g_csr[e];
        float v = g_a1s[s * 8 + h] + ad;
        float w = ex2a(fmaxf(v, 0.2f * v));
        ssum += w;
        union { uint4 u; __half2 q[4]; } pk;
        pk.u = *(const uint4*)(g_h1h + (size_t)s * 64 + h * 8);
        float2 f0 = __half22float2(pk.q[0]);
        float2 f1 = __half22float2(pk.q[1]);
        float2 f2 = __half22float2(pk.q[2]);
        float2 f3 = __half22float2(pk.q[3]);
        A0.x += w * f0.x; A0.y += w * f0.y; A0.z += w * f1.x; A0.w += w * f1.y;
        A1.x += w * f2.x; A1.y += w * f2.y; A1.z += w * f3.x; A1.w += w * f3.y;
    }
    float inv = 1.f / (ssum + 1e-16f);
    const float4* b4 = (const float4*)b1;
    float4 bb0 = b4[h * 2], bb1 = b4[h * 2 + 1];
    float4 r0, r1;
    r0.x = elu1(A0.x * inv + bb0.x); r0.y = elu1(A0.y * inv + bb0.y);
    r0.z = elu1(A0.z * inv + bb0.z); r0.w = elu1(A0.w * inv + bb0.w);
    r1.x = elu1(A1.x * inv + bb1.x); r1.y = elu1(A1.y * inv + bb1.y);
    r1.z = elu1(A1.z * inv + bb1.z); r1.w = elu1(A1.w * inv + bb1.w);
    float* op = g_hm + (size_t)n * 64 + h * 8;
    ((float4*)op)[0] = r0;
    ((float4*)op)[1] = r1;
}

// ---------------- GEMM2: h2 = hm @ W2 (+ scaled att-dot epilogue) ----------
__global__ __launch_bounds__(256) void k_gemm2(
    const float* __restrict__ W2, const float* __restrict__ as2,
    const float* __restrict__ ad2, int N)
{
    __shared__ __align__(16) float Ws[64][40];
    __shared__ __align__(16) float xsT[16][260];
    __shared__ float sA[40], sD[40];

    int tid = threadIdx.x;
    if (tid < 40) { sA[tid] = as2[tid] * LOG2E; sD[tid] = ad2[tid] * LOG2E; }
    for (int f = tid; f < 640; f += 256)
        ((float4*)&Ws[0][0])[f] = ((const float4*)W2)[f];

    int rg = tid >> 2;   // 0..63
    int cg = tid & 3;    // 0..3
    int rowBase = blockIdx.x * 256;

    u64 acc[4][5];
#pragma unroll
    for (int i = 0; i < 4; i++)
#pragma unroll
        for (int c = 0; c < 5; c++) acc[i][c] = 0ull;

    const float4* hm4 = (const float4*)g_hm;

    for (int kc = 0; kc < 4; kc++) {
        __syncthreads();
#pragma unroll
        for (int i = 0; i < 4; i++) {
            int f = tid + i * 256;
            int r = f >> 2, q = f & 3;
            int gr = rowBase + r;
            float4 xv = make_float4(0.f, 0.f, 0.f, 0.f);
            if (gr < N) xv = hm4[(size_t)gr * 16 + kc * 4 + q];
            xsT[q * 4 + 0][r] = xv.x;
            xsT[q * 4 + 1][r] = xv.y;
            xsT[q * 4 + 2][r] = xv.z;
            xsT[q * 4 + 3][r] = xv.w;
        }
        __syncthreads();
#pragma unroll
        for (int kk = 0; kk < 16; kk++) {
            float4 xv = *(const float4*)&xsT[kk][rg * 4];
            const u64* wp = (const u64*)&Ws[kc * 16 + kk][cg * 10];
            u64 w0 = wp[0], w1 = wp[1], w2 = wp[2], w3 = wp[3], w4 = wp[4];
            u64 xd[4] = {dup2(xv.x), dup2(xv.y), dup2(xv.z), dup2(xv.w)};
#pragma unroll
            for (int i = 0; i < 4; i++) {
                fma2(acc[i][0], xd[i], w0);
                fma2(acc[i][1], xd[i], w1);
                fma2(acc[i][2], xd[i], w2);
                fma2(acc[i][3], xd[i], w3);
                fma2(acc[i][4], xd[i], w4);
            }
        }
    }

#pragma unroll
    for (int i = 0; i < 4; i++) {
        int row = rowBase + rg * 4 + i;
        float o[10];
#pragma unroll
        for (int c = 0; c < 5; c++) {
            float2 v = un2(acc[i][c]);
            o[2 * c] = v.x; o[2 * c + 1] = v.y;
        }
        float ps = 0.f, pd = 0.f;
#pragma unroll
        for (int c = 0; c < 10; c++) {
            ps += o[c] * sA[cg * 10 + c];
            pd += o[c] * sD[cg * 10 + c];
        }
        ps += __shfl_xor_sync(0xffffffffu, ps, 1);
        ps += __shfl_xor_sync(0xffffffffu, ps, 2);
        pd += __shfl_xor_sync(0xffffffffu, pd, 1);
        pd += __shfl_xor_sync(0xffffffffu, pd, 2);
        if (row < N) {
            __half2* hp = (__half2*)(g_h2h + (size_t)row * 40 + cg * 10);
#pragma unroll
            for (int c = 0; c < 5; c++)
                hp[c] = __floats2half2_rn(o[2 * c], o[2 * c + 1]);
            if (cg == 0) { g_a2s[row] = ps; g_a2d[row] = pd; }
        }
    }
}

// ---- layer-2 gather: 8 lanes/node, 5 fp16 classes/lane, log_softmax -------
__global__ __launch_bounds__(256) void k_gather2(
    const float* __restrict__ b2, float* __restrict__ out, int N)
{
    int t = blockIdx.x * 256 + threadIdx.x;
    int n = t >> 3, p = t & 7;
    bool valid = (n < N);
    if (!valid) n = N - 1;              // keep lanes alive for shfl
    int beg = g_row[n], end = g_row[n + 1];
    float ad = g_a2d[n];

    float ssum = 0.f;
    float acc[5] = {0.f, 0.f, 0.f, 0.f, 0.f};
    for (int e = beg; e < end; e++) {
        int s = g_csr[e];
        float v = g_a2s[s] + ad;
        float w = ex2a(fmaxf(v, 0.2f * v));
        ssum += w;
        const __half* hp = g_h2h + (size_t)s * 40 + p * 5;
#pragma unroll
        for (int j = 0; j < 5; j++) acc[j] += w * __half2float(hp[j]);
    }
    float inv = 1.f / (ssum + 1e-16f);

    float o[5];
    float mx = -1e30f;
#pragma unroll
    for (int j = 0; j < 5; j++) { o[j] = acc[j] * inv + b2[p * 5 + j]; mx = fmaxf(mx, o[j]); }
#pragma unroll
    for (int msk = 1; msk < 8; msk <<= 1)
        mx = fmaxf(mx, __shfl_xor_sync(0xffffffffu, mx, msk));
    float se = 0.f;
#pragma unroll
    for (int j = 0; j < 5; j++) se += __expf(o[j] - mx);
#pragma unroll
    for (int msk = 1; msk < 8; msk <<= 1)
        se += __shfl_xor_sync(0xffffffffu, se, msk);
    float lse = mx + logf(se);

    if (valid) {
        float* op = out + (size_t)n * 40 + p * 5;
#pragma unroll
        for (int j = 0; j < 5; j++) op[j] = o[j] - lse;
    }
}

// ---------------- launch ----------------
extern "C" void kernel_launch(void* const* d_in, const int* in_sizes, int n_in,
                              void* d_out, int out_size)
{
    const float* x    = (const float*)d_in[0];
    const void*  ei   = d_in[1];
    const float* W1   = (const float*)d_in[2];
    const float* as1  = (const float*)d_in[3];
    const float* ad1  = (const float*)d_in[4];
    const float* b1   = (const float*)d_in[5];
    const float* W2   = (const float*)d_in[6];
    const float* as2  = (const float*)d_in[7];
    const float* ad2  = (const float*)d_in[8];
    const float* b2   = (const float*)d_in[9];
    float*       out  = (float*)d_out;

    int N = in_sizes[0] / F_IN;
    int E = in_sizes[1] / 2;
    int M = E + N;
    int NB = (N + 1023) / 1024;

    static cudaStream_t s_side = nullptr;
    static cudaEvent_t  ev_fork = nullptr, ev_join = nullptr;
    if (!s_side) {
        cudaStreamCreateWithFlags(&s_side, cudaStreamNonBlocking);
        cudaEventCreateWithFlags(&ev_fork, cudaEventDisableTiming);
        cudaEventCreateWithFlags(&ev_join, cudaEventDisableTiming);
    }

    // fork: gemm1 on side stream, concurrent with CSR build
    cudaEventRecord(ev_fork, 0);
    cudaStreamWaitEvent(s_side, ev_fork, 0);
    k_gemm1<<<(N + 127) / 128, 256, 0, s_side>>>(x, W1, as1, ad1, N);
    cudaEventRecord(ev_join, s_side);

    // main chain: CSR build (deg+rank -> lookback-scan -> atomic-free scatter)
    k_deg<<<(E + 255) / 256, 256>>>(ei, E, N);
    k_scan<<<NB, 1024>>>(N, M);
    k_scatter<<<(M + 255) / 256, 256>>>(ei, E, M, N);

    // join, then attention layers
    cudaStreamWaitEvent(0, ev_join, 0);
    k_gather1<<<(N * 8 + 255) / 256, 256>>>(b1, N);
    k_gemm2<<<(N + 255) / 256, 256>>>(W2, as2, ad2, N);
    k_gather2<<<(N * 8 + 255) / 256, 256>>>(b2, out, N);
}